// round 9
// baseline (speedup 1.0000x reference)
#include <cuda_runtime.h>

#define D 256
#define H1 128
#define H2 64

// Folded weights: g_w[0..255] = class-0 column of W1@W2@W3, g_w[256..511] = class 1.
__device__ float g_w[2 * D];
__device__ float g_b[2];

// ---------------------------------------------------------------------------
// Parallel fold (32 blocks x 256 threads):
// Each block redundantly computes W23 = W2@W3 [128,2] in smem (thread/entry,
// 64 serial FMAs), then its 8 warps produce W_eff rows 8b..8b+7 from
// coalesced float4 W1 reads. Block 0 also folds the bias chain.
// W1's 128 KB is fetched in parallel across 32 SMs -> fold is ~2-3 us.
// ---------------------------------------------------------------------------
__global__ void __launch_bounds__(256)
fold_parallel(const float* __restrict__ W1,
              const float* __restrict__ W2,
              const float* __restrict__ W3,
              const float* __restrict__ b1,
              const float* __restrict__ b2,
              const float* __restrict__ b3) {
    __shared__ float sW23c0[H1];
    __shared__ float sW23c1[H1];
    __shared__ float sTvec[H2];

    const int tid  = threadIdx.x;
    const int warp = tid >> 5;      // 0..7
    const int lane = tid & 31;

    // ---- W23: thread tid computes entry (k = tid>>1, c = tid&1) ----
    {
        const int k = tid >> 1;
        const int c = tid & 1;
        const float* w2row = &W2[k * H2];
        float acc = 0.0f;
#pragma unroll 16
        for (int j = 0; j < H2; ++j)
            acc = fmaf(w2row[j], W3[j * 2 + c], acc);
        if (c == 0) sW23c0[k] = acc;
        else        sW23c1[k] = acc;
    }
    __syncthreads();

    // ---- W_eff rows: warp w of block b computes row 8b + w ----
    {
        const int row = blockIdx.x * 8 + warp;      // 0..255
        const float4 a  = *(const float4*)&W1[row * H1 + 4 * lane];
        const float4 c0 = *(const float4*)&sW23c0[4 * lane];
        const float4 c1 = *(const float4*)&sW23c1[4 * lane];

        float s0, s1;
        s0 = a.x * c0.x;            s1 = a.x * c1.x;
        s0 = fmaf(a.y, c0.y, s0);   s1 = fmaf(a.y, c1.y, s1);
        s0 = fmaf(a.z, c0.z, s0);   s1 = fmaf(a.z, c1.z, s1);
        s0 = fmaf(a.w, c0.w, s0);   s1 = fmaf(a.w, c1.w, s1);

#pragma unroll
        for (int o = 16; o > 0; o >>= 1) {
            s0 += __shfl_xor_sync(0xffffffffu, s0, o);
            s1 += __shfl_xor_sync(0xffffffffu, s1, o);
        }
        if (lane == 0) {
            g_w[row]     = s0;
            g_w[D + row] = s1;
        }
    }

    // ---- Bias fold: block 0 only ----
    if (blockIdx.x == 0) {
        // tvec[j] = b2[j] + sum_k b1[k]*W2[k,j]; warp w covers j = 8w..8w+7,
        // each entry as a warp-parallel length-128 dot (4 FMAs/lane + shfl).
#pragma unroll
        for (int jj = 0; jj < 8; ++jj) {
            const int j = warp * 8 + jj;
            float v =      b1[lane]      * W2[(lane)      * H2 + j];
            v = fmaf(b1[lane + 32],  W2[(lane + 32) * H2 + j], v);
            v = fmaf(b1[lane + 64],  W2[(lane + 64) * H2 + j], v);
            v = fmaf(b1[lane + 96],  W2[(lane + 96) * H2 + j], v);
#pragma unroll
            for (int o = 16; o > 0; o >>= 1)
                v += __shfl_xor_sync(0xffffffffu, v, o);
            if (lane == 0) sTvec[j] = v + b2[j];
        }
        __syncthreads();

        if (warp == 0) {
            float t0 = sTvec[lane], t1 = sTvec[lane + 32];
            float bb0 = fmaf(t0, W3[lane * 2 + 0], t1 * W3[(lane + 32) * 2 + 0]);
            float bb1 = fmaf(t0, W3[lane * 2 + 1], t1 * W3[(lane + 32) * 2 + 1]);
#pragma unroll
            for (int o = 16; o > 0; o >>= 1) {
                bb0 += __shfl_xor_sync(0xffffffffu, bb0, o);
                bb1 += __shfl_xor_sync(0xffffffffu, bb1, o);
            }
            if (lane == 0) {
                g_b[0] = bb0 + b3[0];
                g_b[1] = bb1 + b3[1];
            }
        }
    }
}

// ---------------------------------------------------------------------------
// Main kernel: one warp per edge, grid-stride over edges.
// Grid = 8880 = 148 SMs x 60: integer wave count at 5 or 6 CTAs/SM, so no
// wave-quantization tail. Measured at the LTS cap (~13 TB/s through L2).
// ---------------------------------------------------------------------------
__global__ void __launch_bounds__(256)
edge_predict_kernel(const float* __restrict__ h,
                    const int* __restrict__ edges,   // int32 indices
                    float* __restrict__ out, int E) {
    const int lane   = threadIdx.x & 31;
    const int warp   = (blockIdx.x * blockDim.x + threadIdx.x) >> 5;
    const int nwarps = (gridDim.x * blockDim.x) >> 5;

    // Per-lane folded weights, register-resident across all edges.
    const float4 w0a = *(const float4*)&g_w[4 * lane];
    const float4 w0b = *(const float4*)&g_w[128 + 4 * lane];
    const float4 w1a = *(const float4*)&g_w[D + 4 * lane];
    const float4 w1b = *(const float4*)&g_w[D + 128 + 4 * lane];
    const float bias0 = g_b[0];
    const float bias1 = g_b[1];

    for (int e = warp; e < E; e += nwarps) {
        const int2 st = __ldg((const int2*)edges + e);
        const long long s = st.x;
        const long long t = st.y;

        const float4* hs = (const float4*)h + s * (D / 4);
        const float4* ht = (const float4*)h + t * (D / 4);

        const float4 x0 = __ldg(hs + lane);
        const float4 y0 = __ldg(ht + lane);
        const float4 x1 = __ldg(hs + lane + 32);
        const float4 y1 = __ldg(ht + lane + 32);

        float p, a0, a1;
        p = x0.x * y0.x; a0 = p * w0a.x;          a1 = p * w1a.x;
        p = x0.y * y0.y; a0 = fmaf(p, w0a.y, a0); a1 = fmaf(p, w1a.y, a1);
        p = x0.z * y0.z; a0 = fmaf(p, w0a.z, a0); a1 = fmaf(p, w1a.z, a1);
        p = x0.w * y0.w; a0 = fmaf(p, w0a.w, a0); a1 = fmaf(p, w1a.w, a1);
        p = x1.x * y1.x; a0 = fmaf(p, w0b.x, a0); a1 = fmaf(p, w1b.x, a1);
        p = x1.y * y1.y; a0 = fmaf(p, w0b.y, a0); a1 = fmaf(p, w1b.y, a1);
        p = x1.z * y1.z; a0 = fmaf(p, w0b.z, a0); a1 = fmaf(p, w1b.z, a1);
        p = x1.w * y1.w; a0 = fmaf(p, w0b.w, a0); a1 = fmaf(p, w1b.w, a1);

#pragma unroll
        for (int o = 16; o > 0; o >>= 1) {
            a0 += __shfl_xor_sync(0xffffffffu, a0, o);
            a1 += __shfl_xor_sync(0xffffffffu, a1, o);
        }

        if (lane == 0) {
            a0 += bias0;
            a1 += bias1;
            float m  = fmaxf(a0, a1);
            float e0 = expf(a0 - m);
            float e1 = expf(a1 - m);
            float inv = 1.0f / (e0 + e1);
            ((float2*)out)[e] = make_float2(e0 * inv, e1 * inv);
        }
    }
}

extern "C" void kernel_launch(void* const* d_in, const int* in_sizes, int n_in,
                              void* d_out, int out_size) {
    const float* h     = (const float*)d_in[0];
    const int*   edges = (const int*)d_in[1];
    const float* W1    = (const float*)d_in[2];
    const float* b1    = (const float*)d_in[3];
    const float* W2    = (const float*)d_in[4];
    const float* b2    = (const float*)d_in[5];
    const float* W3    = (const float*)d_in[6];
    const float* b3    = (const float*)d_in[7];
    float*       out   = (float*)d_out;

    const int E = in_sizes[1] / 2;

    fold_parallel<<<32, 256>>>(W1, W2, W3, b1, b2, b3);
    // 8880 = 148 x 60: integer number of waves at 5 or 6 resident CTAs/SM.
    edge_predict_kernel<<<8880, 256>>>(h, edges, out, E);
}